// round 3
// baseline (speedup 1.0000x reference)
#include <cuda_runtime.h>

#define FULL_MASK 0xFFFFFFFFu

// Packed fp32x2 FMA (Blackwell): d = a*b + d on both 32-bit halves.
__device__ __forceinline__ void fma2(unsigned long long& d,
                                     unsigned long long a,
                                     unsigned long long b) {
    asm("fma.rn.f32x2 %0, %1, %2, %0;" : "+l"(d) : "l"(a), "l"(b));
}

// One warp per vertex. 8 warps (= 8 vertices) per 256-thread block.
// Phase A: lane = neighbor k -> compute 9 Gaussian weights, stash duplicated
//          float2 {w,w} in smem (enables FFMA2 without packing MOVs).
// Phase B: lane = feature pair (f=2*lane, 2*lane+1) -> 9x32 FFMA2 accumulation,
//          features gathered directly from global (coalesced 256B rows, L2-resident).
__global__ void __launch_bounds__(256)
softpixel_kernel(const float* __restrict__ coords,   // [V,4]
                 const float* __restrict__ feats,    // [V,64]
                 const int*   __restrict__ nidx,     // [V,32]
                 const float* __restrict__ lsp,      // [1]
                 float*       __restrict__ out,      // [V,576]
                 int V)
{
    __shared__ float2 wsm[8][9][32];   // 18 KB/block

    const int warp = threadIdx.x >> 5;
    const int lane = threadIdx.x & 31;
    const int v = blockIdx.x * 8 + warp;
    if (v >= V) return;

    const float ls = __ldg(lsp);
    const float a  = -10.0f * ls;          // ACCUMULATE_KNN_EXPONENT
    const float s  = 1.0f / 32.0f;         // fold mean-over-K into weights

    // ---------------- Phase A: weights (lane == neighbor index k) -----------
    const int nb = nidx[v * 32 + lane];
    const float4 cn = *reinterpret_cast<const float4*>(coords + 4 * nb);
    const float4 cv = *reinterpret_cast<const float4*>(coords + 4 * v);
    const float d0 = cv.x - cn.x;
    const float d1 = cv.y - cn.y;
    const float d2 = cv.z - cn.z;
    const float d3 = cv.w - cn.w;
    const float base = d0*d0 + d1*d1 + d2*d2 + d3*d3;
    const float b1 = base + 1.0f;          // ||o||^2 = 1 for the 8 axis offsets

    float w[9];
    // Offset order derived from SoftPixelCNN.create_offsets('onlyaxes', D=4, sub=3):
    // 0:(0,0,0,0) 1:(0,-1,0,0) 2:(-1,0,0,0) 3:(0,0,-1,0) 4:(0,0,0,-1)
    // 5:(0,0,0,+1) 6:(0,0,+1,0) 7:(+1,0,0,0) 8:(0,+1,0,0)
    w[0] = __expf(a * base) * s;
    w[1] = __expf(a * (b1 - 2.0f * d1)) * s;
    w[2] = __expf(a * (b1 - 2.0f * d0)) * s;
    w[3] = __expf(a * (b1 - 2.0f * d2)) * s;
    w[4] = __expf(a * (b1 - 2.0f * d3)) * s;
    w[5] = __expf(a * (b1 + 2.0f * d3)) * s;
    w[6] = __expf(a * (b1 + 2.0f * d2)) * s;
    w[7] = __expf(a * (b1 + 2.0f * d0)) * s;
    w[8] = __expf(a * (b1 + 2.0f * d1)) * s;

    #pragma unroll
    for (int o = 0; o < 9; ++o)
        wsm[warp][o][lane] = make_float2(w[o], w[o]);
    __syncwarp();

    // ---------------- Phase B: accumulate (lane == f-pair) ------------------
    unsigned long long acc[9];
    #pragma unroll
    for (int o = 0; o < 9; ++o) acc[o] = 0ull;   // packed {0.f, 0.f}

    const int fofs = 2 * lane;
    const unsigned long long* wrow =
        reinterpret_cast<const unsigned long long*>(&wsm[warp][0][0]);

    #pragma unroll
    for (int k0 = 0; k0 < 32; k0 += 4) {
        unsigned long long g[4];
        #pragma unroll
        for (int j = 0; j < 4; ++j) {
            const int nbk = __shfl_sync(FULL_MASK, nb, k0 + j);
            g[j] = *reinterpret_cast<const unsigned long long*>(
                       feats + nbk * 64 + fofs);
        }
        #pragma unroll
        for (int j = 0; j < 4; ++j) {
            #pragma unroll
            for (int o = 0; o < 9; ++o) {
                fma2(acc[o], wrow[o * 32 + (k0 + j)], g[j]);
            }
        }
    }

    // ---------------- Store: out[v][o*64 + f] -------------------------------
    float* orow = out + (long long)v * 576 + fofs;
    #pragma unroll
    for (int o = 0; o < 9; ++o) {
        *reinterpret_cast<float2*>(orow + o * 64) =
            *reinterpret_cast<float2*>(&acc[o]);
    }
}

extern "C" void kernel_launch(void* const* d_in, const int* in_sizes, int n_in,
                              void* d_out, int out_size) {
    const float* coords = (const float*)d_in[0];   // [V,4]
    const float* feats  = (const float*)d_in[1];   // [V,64]
    // d_in[2] = distsq — unused on the inference path (stop_gradient EMA input)
    const int*   nidx   = (const int*)d_in[3];     // [V,32]
    const float* lsp    = (const float*)d_in[4];   // [1]
    float* out = (float*)d_out;

    const int V = in_sizes[0] / 4;
    const int blocks = (V + 7) / 8;                // 8 vertices (warps) per block
    softpixel_kernel<<<blocks, 256>>>(coords, feats, nidx, lsp, out, V);
}

// round 4
// speedup vs baseline: 1.4063x; 1.4063x over previous
#include <cuda_runtime.h>

#define FULL_MASK 0xFFFFFFFFu

// Packed fp32x2 FMA (Blackwell): d = a*b + d on both 32-bit halves.
__device__ __forceinline__ void fma2(unsigned long long& d,
                                     unsigned long long a,
                                     unsigned long long b) {
    asm("fma.rn.f32x2 %0, %1, %2, %0;" : "+l"(d) : "l"(a), "l"(b));
}

// 128 threads = 4 warps per block. Each warp handles TWO vertices:
//   lanes 0-15  -> vertex vbase+0, lanes 16-31 -> vertex vbase+1.
// Phase A: each lane computes the 9 Gaussian weights for 2 neighbors
//          (k = l and k = l+16 of its vertex) and writes duplicated {w,w}
//          float2 pairs to smem laid out [k][o] (o padded to 10) so that
//          Phase B reads them as 5x LDS.128 per k.
// Phase B: lane = 4-feature slice (f = 4*l .. 4*l+3). Per k: 5 LDS.128
//          (weights, broadcast per half, bank-shifted pad -> conflict-free)
//          + 1 LDG.128 (feature row slice, coalesced per half) + 18 FFMA2.
//          Weight-broadcast cost amortized over 4 output floats per lane.

static constexpr int WROW   = 10;              // 9 offsets + 1 pad (float2 units)
static constexpr int HSTRIDE = 32 * WROW + 2;  // +2 float2 = 16B pad: shifts banks
                                               // by 4 between the two halves

__global__ void __launch_bounds__(128, 5)
softpixel_kernel(const float* __restrict__ coords,   // [V,4]
                 const float* __restrict__ feats,    // [V,64]
                 const int*   __restrict__ nidx,     // [V,32]
                 const float* __restrict__ lsp,      // [1]
                 float*       __restrict__ out,      // [V,576]
                 int V)
{
    __shared__ __align__(16) float2 wsm[4][2][HSTRIDE];   // ~20.6 KB/block

    const int warp = threadIdx.x >> 5;
    const int lane = threadIdx.x & 31;
    const int half = lane >> 4;        // which vertex of the pair
    const int l    = lane & 15;

    const int vraw = blockIdx.x * 8 + warp * 2 + half;
    const int v    = vraw < V ? vraw : V - 1;   // clamp: full-warp participation

    const float ls = __ldg(lsp);
    const float a  = -10.0f * ls;      // ACCUMULATE_KNN_EXPONENT
    const float s  = 1.0f / 32.0f;     // fold mean-over-K into weights

    // ---------------- Phase A: weights ------------------------------------
    const float4 cv = *reinterpret_cast<const float4*>(coords + 4 * v);
    const int nb0 = nidx[v * 32 + l];
    const int nb1 = nidx[v * 32 + l + 16];

    float2* wbase = &wsm[warp][half][0];

    #pragma unroll
    for (int t = 0; t < 2; ++t) {
        const int kk = l + 16 * t;
        const int nb = t ? nb1 : nb0;
        const float4 cn = *reinterpret_cast<const float4*>(coords + 4 * nb);
        const float d0 = cv.x - cn.x;
        const float d1 = cv.y - cn.y;
        const float d2 = cv.z - cn.z;
        const float d3 = cv.w - cn.w;
        const float base = d0*d0 + d1*d1 + d2*d2 + d3*d3;
        const float b1 = base + 1.0f;  // ||o||^2 = 1 for the 8 axis offsets

        float w[9];
        // Offset order from SoftPixelCNN.create_offsets('onlyaxes', D=4, sub=3):
        // 0:(0,0,0,0) 1:(0,-1,0,0) 2:(-1,0,0,0) 3:(0,0,-1,0) 4:(0,0,0,-1)
        // 5:(0,0,0,+1) 6:(0,0,+1,0) 7:(+1,0,0,0) 8:(0,+1,0,0)
        w[0] = __expf(a * base) * s;
        w[1] = __expf(a * (b1 - 2.0f * d1)) * s;
        w[2] = __expf(a * (b1 - 2.0f * d0)) * s;
        w[3] = __expf(a * (b1 - 2.0f * d2)) * s;
        w[4] = __expf(a * (b1 - 2.0f * d3)) * s;
        w[5] = __expf(a * (b1 + 2.0f * d3)) * s;
        w[6] = __expf(a * (b1 + 2.0f * d2)) * s;
        w[7] = __expf(a * (b1 + 2.0f * d0)) * s;
        w[8] = __expf(a * (b1 + 2.0f * d1)) * s;

        #pragma unroll
        for (int o = 0; o < 9; ++o)
            wbase[kk * WROW + o] = make_float2(w[o], w[o]);
    }
    __syncwarp();

    // ---------------- Phase B: accumulate ----------------------------------
    unsigned long long acc[9][2];
    #pragma unroll
    for (int o = 0; o < 9; ++o) { acc[o][0] = 0ull; acc[o][1] = 0ull; }

    const int fofs = 4 * l;            // this lane's 4-feature slice

    #pragma unroll
    for (int k0 = 0; k0 < 32; k0 += 4) {
        // gather 4 neighbor feature slices (front-batched LDGs, MLP=4)
        ulonglong2 g[4];
        #pragma unroll
        for (int j = 0; j < 4; ++j) {
            const int k = k0 + j;
            const int src = half * 16 + (k & 15);
            const int nbk = __shfl_sync(FULL_MASK, (k < 16) ? nb0 : nb1, src);
            g[j] = *reinterpret_cast<const ulonglong2*>(feats + nbk * 64 + fofs);
        }
        #pragma unroll
        for (int j = 0; j < 4; ++j) {
            const int k = k0 + j;
            const ulonglong2* wr =
                reinterpret_cast<const ulonglong2*>(wbase + k * WROW);
            const ulonglong2 wA = wr[0];   // {w0,w0},{w1,w1}
            const ulonglong2 wB = wr[1];   // w2,w3
            const ulonglong2 wC = wr[2];   // w4,w5
            const ulonglong2 wD = wr[3];   // w6,w7
            const unsigned long long w8 =
                reinterpret_cast<const unsigned long long*>(wr)[8];

            fma2(acc[0][0], wA.x, g[j].x);  fma2(acc[0][1], wA.x, g[j].y);
            fma2(acc[1][0], wA.y, g[j].x);  fma2(acc[1][1], wA.y, g[j].y);
            fma2(acc[2][0], wB.x, g[j].x);  fma2(acc[2][1], wB.x, g[j].y);
            fma2(acc[3][0], wB.y, g[j].x);  fma2(acc[3][1], wB.y, g[j].y);
            fma2(acc[4][0], wC.x, g[j].x);  fma2(acc[4][1], wC.x, g[j].y);
            fma2(acc[5][0], wC.y, g[j].x);  fma2(acc[5][1], wC.y, g[j].y);
            fma2(acc[6][0], wD.x, g[j].x);  fma2(acc[6][1], wD.x, g[j].y);
            fma2(acc[7][0], wD.y, g[j].x);  fma2(acc[7][1], wD.y, g[j].y);
            fma2(acc[8][0], w8,   g[j].x);  fma2(acc[8][1], w8,   g[j].y);
        }
    }

    // ---------------- Store: out[v][o*64 + f] -------------------------------
    float* orow = out + (long long)v * 576 + fofs;
    #pragma unroll
    for (int o = 0; o < 9; ++o) {
        ulonglong2 r;
        r.x = acc[o][0];
        r.y = acc[o][1];
        *reinterpret_cast<ulonglong2*>(orow + o * 64) = r;
    }
}

extern "C" void kernel_launch(void* const* d_in, const int* in_sizes, int n_in,
                              void* d_out, int out_size) {
    const float* coords = (const float*)d_in[0];   // [V,4]
    const float* feats  = (const float*)d_in[1];   // [V,64]
    // d_in[2] = distsq — unused on the inference path (stop_gradient EMA input)
    const int*   nidx   = (const int*)d_in[3];     // [V,32]
    const float* lsp    = (const float*)d_in[4];   // [1]
    float* out = (float*)d_out;

    const int V = in_sizes[0] / 4;
    const int blocks = (V + 7) / 8;                // 8 vertices per 128-thread block
    softpixel_kernel<<<blocks, 128>>>(coords, feats, nidx, lsp, out, V);
}